// round 1
// baseline (speedup 1.0000x reference)
#include <cuda_runtime.h>
#include <cstdint>
#include <cstddef>

#define BB 1024
#define FF 4096
#define DD 32

#define ROWGROUPS 16     // 64 rows each
#define CHUNKS 16        // F chunks of 256
#define ROWS_PB 64       // rows per block (= per warp)
#define F_PB 256         // f per block
#define WARPS 8
#define F_PW 32          // f per warp
#define TILE_PAD 65      // 64 rows + 1 pad word -> conflict-free transpose
#define TILE_FLOATS (33*65)   // 2145 floats: holds 32x65 tile AND 64x33 red buffer
#define RED_SZ (64*33)

// partial scratch: s partials [chunk][row][d], bias partials [chunk][row]
__device__ float g_ps[(size_t)CHUNKS * BB * DD];
__device__ float g_pb[(size_t)CHUNKS * BB];

// dynamic smem layout (floats):
//   [0,     8192)  embed slice: 256 f x 32 d
//   [8192,  8448)  bias slice: 256 f
//   [8448,  ...)   8 warp-private tiles (each TILE_FLOATS), reused as reduction buffers
__global__ void __launch_bounds__(256, 2)
fm_main(const float* __restrict__ data,
        const float* __restrict__ embed,
        const float* __restrict__ bias)
{
    extern __shared__ float sm[];
    float* s_embed = sm;
    float* s_bias  = sm + 8192;
    float* s_tiles = sm + 8448;

    const int tid  = threadIdx.x;
    const int w    = tid >> 5;
    const int lane = tid & 31;
    const int rg   = blockIdx.x & 15;
    const int ck   = blockIdx.x >> 4;
    const int rowbase = rg * ROWS_PB;
    const int fblk    = ck * F_PB;

    // ---- cooperative load of embed slice (256x32 = 32KB) and bias slice ----
    {
        const float4* eg = reinterpret_cast<const float4*>(embed + (size_t)fblk * DD);
        float4* es = reinterpret_cast<float4*>(s_embed);
        #pragma unroll
        for (int k = 0; k < 8; k++)
            es[tid + k * 256] = eg[tid + k * 256];
        s_bias[tid] = bias[fblk + tid];
    }

    // ---- stage data tile (warp-private transpose: [f][row], pad 65) ----
    float* tile = s_tiles + w * TILE_FLOATS;
    {
        const int fw = fblk + w * F_PW;
        const int r0 = lane >> 3;        // 0..3
        const int fq = (lane & 7) << 2;  // 0,4,...,28
        #pragma unroll
        for (int rr = 0; rr < ROWS_PB; rr += 4) {
            const int row = rr + r0;
            const float4 v = *reinterpret_cast<const float4*>(
                data + (size_t)(rowbase + row) * FF + fw + fq);
            tile[(fq + 0) * TILE_PAD + row] = v.x;
            tile[(fq + 1) * TILE_PAD + row] = v.y;
            tile[(fq + 2) * TILE_PAD + row] = v.z;
            tile[(fq + 3) * TILE_PAD + row] = v.w;
        }
    }
    __syncthreads();

    // ---- main loop: f32x2 packed FMA, lane owns rows {lane, lane+32} ----
    unsigned long long accA[16], accB[16];  // (s[row][2dp], s[row][2dp+1]) pairs
    #pragma unroll
    for (int i = 0; i < 16; i++) { accA[i] = 0ull; accB[i] = 0ull; }
    float bacc0 = 0.f, bacc1 = 0.f;

    const float* ebase = s_embed + (w * F_PW) * DD;
    const float* bbase = s_bias + w * F_PW;

    #pragma unroll 4
    for (int fi = 0; fi < F_PW; fi++) {
        const float d0 = tile[fi * TILE_PAD + lane];
        const float d1 = tile[fi * TILE_PAD + lane + 32];
        unsigned long long dv0, dv1;
        asm("mov.b64 %0, {%1, %1};" : "=l"(dv0) : "f"(d0));
        asm("mov.b64 %0, {%1, %1};" : "=l"(dv1) : "f"(d1));
        const float bf = bbase[fi];
        bacc0 = fmaf(d0, bf, bacc0);
        bacc1 = fmaf(d1, bf, bacc1);
        const unsigned long long* ev =
            reinterpret_cast<const unsigned long long*>(ebase + fi * DD);
        #pragma unroll
        for (int dp = 0; dp < 16; dp++) {
            const unsigned long long e = ev[dp];  // LDS.64, 128B-aligned rows
            asm("fma.rn.f32x2 %0, %1, %2, %0;" : "+l"(accA[dp]) : "l"(dv0), "l"(e));
            asm("fma.rn.f32x2 %0, %1, %2, %0;" : "+l"(accB[dp]) : "l"(dv1), "l"(e));
        }
    }

    // ---- dump per-warp partials into own tile region: red[row*33 + d], d=32 bias ----
    {
        float* red = tile;
        #pragma unroll
        for (int dp = 0; dp < 16; dp++) {
            float a0, a1, b0, b1;
            asm("mov.b64 {%0, %1}, %2;" : "=f"(a0), "=f"(a1) : "l"(accA[dp]));
            asm("mov.b64 {%0, %1}, %2;" : "=f"(b0), "=f"(b1) : "l"(accB[dp]));
            red[lane * 33 + 2 * dp]            = a0;
            red[lane * 33 + 2 * dp + 1]        = a1;
            red[(lane + 32) * 33 + 2 * dp]     = b0;
            red[(lane + 32) * 33 + 2 * dp + 1] = b1;
        }
        red[lane * 33 + 32]        = bacc0;
        red[(lane + 32) * 33 + 32] = bacc1;
    }
    __syncthreads();

    // ---- block-level tree reduction across 8 warps, write global partials ----
    for (int i = tid; i < RED_SZ; i += 256) {
        float s = 0.f;
        #pragma unroll
        for (int ww = 0; ww < WARPS; ww++)
            s += s_tiles[ww * TILE_FLOATS + i];
        const int row = i / 33;
        const int d   = i - row * 33;
        const int grow = rowbase + row;
        if (d < 32) g_ps[((size_t)ck * BB + grow) * DD + d] = s;
        else        g_pb[(size_t)ck * BB + grow] = s;
    }
}

// ---- finisher: warp per row; coalesced partial reads; sigmoid ----
__global__ void __launch_bounds__(256)
fm_finish(const float* __restrict__ gbias, float* __restrict__ out)
{
    const int w    = threadIdx.x >> 5;
    const int lane = threadIdx.x & 31;
    const int row  = blockIdx.x * 8 + w;

    float s = 0.f;
    #pragma unroll
    for (int c = 0; c < CHUNKS; c++)
        s += g_ps[((size_t)c * BB + row) * DD + lane];

    float t = s * s;
    if (lane < CHUNKS)
        t += g_pb[(size_t)lane * BB + row];

    #pragma unroll
    for (int o = 16; o; o >>= 1)
        t += __shfl_xor_sync(0xffffffffu, t, o);

    if (lane == 0) {
        const float x = gbias[0] + t;
        out[row] = 1.0f / (1.0f + __expf(-x));
    }
}

extern "C" void kernel_launch(void* const* d_in, const int* in_sizes, int n_in,
                              void* d_out, int out_size)
{
    const float* data  = (const float*)d_in[0];
    const float* embed = (const float*)d_in[1];
    const float* bias  = (const float*)d_in[2];
    const float* gb    = (const float*)d_in[3];
    float* out = (float*)d_out;

    const int smem_bytes = (8192 + 256 + WARPS * TILE_FLOATS) * (int)sizeof(float);
    cudaFuncSetAttribute(fm_main, cudaFuncAttributeMaxDynamicSharedMemorySize, smem_bytes);

    fm_main<<<ROWGROUPS * CHUNKS, 256, smem_bytes>>>(data, embed, bias);
    fm_finish<<<BB / 8, 256>>>(gb, out);
}